// round 7
// baseline (speedup 1.0000x reference)
#include <cuda_runtime.h>
#include <cuda_bf16.h>

// Problem constants (fixed by the reference): N=100000, M=8, K=256, D=64
#define PQ_N 100000
#define PQ_M 8
#define PQ_K 256
#define PQ_D 64
#define NTILE 512          // n-rows per block (1 per thread, 512 threads)
#define THREADS 512

// ---------------- packed f32x2 helpers ----------------
__device__ __forceinline__ unsigned long long pack2(float a) {
    unsigned long long r;
    asm("mov.b64 %0, {%1, %1};" : "=l"(r) : "f"(a));
    return r;
}
__device__ __forceinline__ void ffma2(unsigned long long &d,
                                      unsigned long long a,
                                      unsigned long long b) {
    asm("fma.rn.f32x2 %0, %1, %2, %0;" : "+l"(d) : "l"(a), "l"(b));
}
__device__ __forceinline__ float2 unpack2(unsigned long long v) {
    float2 f;
    asm("mov.b64 {%0, %1}, %2;" : "=f"(f.x), "=f"(f.y) : "l"(v));
    return f;
}

// NEON/LLVM-emulated sum of squares over 64 contiguous values (VF=4, IC=2,
// separate rn-mul / rn-add, faddp-style horizontal) — matches reference c_sq/x_sq.
__device__ __forceinline__ float neon_sumsq64(const float* v) {
    float a0[4] = {0.f, 0.f, 0.f, 0.f};
    float a1[4] = {0.f, 0.f, 0.f, 0.f};
    #pragma unroll
    for (int i = 0; i < 8; ++i) {
        #pragma unroll
        for (int l = 0; l < 4; ++l) {
            a0[l] = __fadd_rn(a0[l], __fmul_rn(v[8 * i + l],     v[8 * i + l]));
            a1[l] = __fadd_rn(a1[l], __fmul_rn(v[8 * i + 4 + l], v[8 * i + 4 + l]));
        }
    }
    float s0 = __fadd_rn(a0[0], a1[0]);
    float s1 = __fadd_rn(a0[1], a1[1]);
    float s2 = __fadd_rn(a0[2], a1[2]);
    float s3 = __fadd_rn(a0[3], a1[3]);
    return __fadd_rn(__fadd_rn(s0, s1), __fadd_rn(s2, s3));
}

// smem layout (floats):
//   cs   [64][256]   transposed codebook                      16384
//   xs   [64][NTILE] transposed x tile, PRE-NEGATED (-x)      32768
//   csq  [256]       ||c_k||^2 (NEON order, refinement)         256
//   scsq [256]       0.5*||c_k||^2 (accumulator init)           256
//   xsqs [NTILE]     ||x_n||^2 (NEON order, refinement)         512
#define SM_CS   0
#define SM_XS   (64 * 256)
#define SM_CSQ  (SM_XS + 64 * NTILE)
#define SM_SCSQ (SM_CSQ + 256)
#define SM_XSQ  (SM_SCSQ + 256)
#define SM_FLOATS (SM_XSQ + NTILE)

extern "C" __global__ void __launch_bounds__(THREADS, 1)
pq_encode_kernel(const float* __restrict__ x,
                 const float* __restrict__ cb,
                 float* __restrict__ qout,
                 float* __restrict__ idf,
                 long long* __restrict__ idl,
                 int id_mode)
{
    extern __shared__ float smem[];
    float* cs   = smem + SM_CS;
    float* xs   = smem + SM_XS;
    float* csq  = smem + SM_CSQ;
    float* scsq = smem + SM_SCSQ;
    float* xsqs = smem + SM_XSQ;

    const int m   = blockIdx.y;
    const int tid = threadIdx.x;
    const int n0  = blockIdx.x * NTILE;

    // ---- stage codebook m (transposed); c_sq via NEON reduce (tid<256) ----
    if (tid < 256) {
        const float4* src = reinterpret_cast<const float4*>(
            cb + (size_t)m * PQ_K * PQ_D + (size_t)tid * PQ_D);
        float cw[64];
        #pragma unroll
        for (int d4 = 0; d4 < 16; ++d4) {
            float4 v = src[d4];
            int d = d4 * 4;
            cw[d + 0] = v.x; cw[d + 1] = v.y; cw[d + 2] = v.z; cw[d + 3] = v.w;
            cs[(d + 0) * 256 + tid] = v.x;
            cs[(d + 1) * 256 + tid] = v.y;
            cs[(d + 2) * 256 + tid] = v.z;
            cs[(d + 3) * 256 + tid] = v.w;
        }
        float sq = neon_sumsq64(cw);
        csq[tid]  = sq;
        scsq[tid] = 0.5f * sq;   // exact (power-of-two scale)
    }

    // ---- stage x row (1 per thread), transposed + NEGATED; x_sq via NEON ----
    {
        const int n = n0 + tid;
        float xw[64];
        if (n < PQ_N) {
            const float4* gx = reinterpret_cast<const float4*>(
                x + (size_t)n * (PQ_M * PQ_D) + (size_t)m * PQ_D);
            #pragma unroll
            for (int d4 = 0; d4 < 16; ++d4) {
                float4 v = gx[d4];
                xw[d4 * 4 + 0] = v.x; xw[d4 * 4 + 1] = v.y;
                xw[d4 * 4 + 2] = v.z; xw[d4 * 4 + 3] = v.w;
            }
        } else {
            #pragma unroll
            for (int d = 0; d < 64; ++d) xw[d] = 0.f;
        }
        #pragma unroll
        for (int d = 0; d < 64; ++d) xs[d * NTILE + tid] = -xw[d];  // pre-negated
        xsqs[tid] = neon_sumsq64(xw);   // squares: sign-invariant
    }
    __syncthreads();

    // FAST PASS: score_k = 0.5*||c_k||^2 - x.c_k, fused seq FMA chain over d
    // ascending (init 0.5*csq). Ordering-equivalent to dist outside the window.
    float best = 3.402823466e38f, second = 3.402823466e38f;
    int ibest = 0, isec = 0;

    // ---- 4 chunks of 32 k-pairs (64 codewords each), ascending k ----
    #pragma unroll 1
    for (int kc = 0; kc < 256; kc += 64) {
        unsigned long long acc[32];
        const unsigned long long* q0 =
            reinterpret_cast<const unsigned long long*>(scsq + kc);
        #pragma unroll
        for (int j = 0; j < 32; ++j) acc[j] = q0[j];  // init = 0.5*csq pairs

        #pragma unroll 4
        for (int d = 0; d < 64; ++d) {
            unsigned long long x2 = pack2(xs[d * NTILE + tid]);  // already -x
            const ulonglong2* cp =
                reinterpret_cast<const ulonglong2*>(cs + d * 256 + kc);
            #pragma unroll
            for (int j = 0; j < 16; ++j) {
                ulonglong2 c2 = cp[j];      // one LDS.128 feeds 2 FFMA2
                ffma2(acc[2 * j],     x2, c2.x);
                ffma2(acc[2 * j + 1], x2, c2.y);
            }
        }

        #pragma unroll
        for (int j = 0; j < 32; ++j) {
            float2 s = unpack2(acc[j]);
            int k0 = kc + 2 * j;
            if (s.x < best)        { second = best; isec = ibest; best = s.x; ibest = k0; }
            else if (s.x < second) { second = s.x;  isec = k0; }
            if (s.y < best)        { second = best; isec = ibest; best = s.y; ibest = k0 + 1; }
            else if (s.y < second) { second = s.y;  isec = k0 + 1; }
        }
    }

    const int n = n0 + tid;
    if (n >= PQ_N) return;

    // ---- REFINEMENT (frozen, verified exact vs reference): dot = separate
    // rn-mul + rn-add chain over d ascending; dist left-assoc; tie -> lower k.
    // Score-gap 0.75e-3 == dist-gap 1.5e-3 window. xs holds -x: negate back
    // (exact sign flip, preserves every rounding).
    if (second - best < 0.75e-3f) {
        float ea = 0.f, eb = 0.f;
        #pragma unroll 4
        for (int d = 0; d < 64; ++d) {
            float xv = -xs[d * NTILE + tid];
            ea = __fadd_rn(ea, __fmul_rn(xv, cs[d * 256 + ibest]));
            eb = __fadd_rn(eb, __fmul_rn(xv, cs[d * 256 + isec]));
        }
        float xsq = xsqs[tid];
        float da = __fadd_rn(__fsub_rn(xsq, __fmul_rn(2.0f, ea)), csq[ibest]);
        float db = __fadd_rn(__fsub_rn(xsq, __fmul_rn(2.0f, eb)), csq[isec]);
        if (db < da || (db == da && isec < ibest)) ibest = isec;
    }

    // ---- write Q row (selected codeword) ----
    float* qrow = qout + (size_t)n * (PQ_M * PQ_D) + (size_t)m * PQ_D;
    #pragma unroll
    for (int d4 = 0; d4 < 16; ++d4) {
        float4 v;
        v.x = cs[(d4 * 4 + 0) * 256 + ibest];
        v.y = cs[(d4 * 4 + 1) * 256 + ibest];
        v.z = cs[(d4 * 4 + 2) * 256 + ibest];
        v.w = cs[(d4 * 4 + 3) * 256 + ibest];
        reinterpret_cast<float4*>(qrow)[d4] = v;
    }

    // ---- write id (layout id_x[m][n]) ----
    if (id_mode == 1) {
        idf[(size_t)m * PQ_N + n] = (float)ibest;
    } else if (id_mode == 2) {
        idl[(size_t)m * PQ_N + n] = (long long)ibest;
    }
}

extern "C" void kernel_launch(void* const* d_in, const int* in_sizes, int n_in,
                              void* d_out, int out_size) {
    const float* x  = (const float*)d_in[0];   // (N, 512) f32
    const float* cb = (const float*)d_in[1];   // (8, 256, 64) f32

    float* out = (float*)d_out;
    const long long QN  = (long long)PQ_N * PQ_M * PQ_D;  // 51,200,000
    const long long IDN = (long long)PQ_M * PQ_N;         // 800,000

    int id_mode = 0;
    float* idf = nullptr;
    long long* idl = nullptr;
    long long osz = (long long)out_size;
    if (osz >= QN + 2 * IDN) {
        id_mode = 2;
        idl = reinterpret_cast<long long*>(out + QN);
    } else if (osz >= QN + IDN) {
        id_mode = 1;
        idf = out + QN;
    }

    const int smem_bytes = SM_FLOATS * sizeof(float);  // ~196KB
    cudaFuncSetAttribute(pq_encode_kernel,
                         cudaFuncAttributeMaxDynamicSharedMemorySize, smem_bytes);

    dim3 grid((PQ_N + NTILE - 1) / NTILE, PQ_M);
    pq_encode_kernel<<<grid, THREADS, smem_bytes>>>(x, cb, out, idf, idl, id_mode);
}